// round 4
// baseline (speedup 1.0000x reference)
#include <cuda_runtime.h>

#define W 512
#define H 512
#define BATCH 2
#define HW (H*W)
#define NCV (BATCH*(H-1)*W)
#define NCH (BATCH*H*(W-1))
#define L_STEP 0.24f
#define KK 0.0009f   /* 0.03*0.03 */

#define TW 128
#define TH 64
#define HALO 8
#define TSX (TW - 2*HALO)   /* 112 interior width  */
#define TSY (TH - 2*HALO)   /* 48  interior height */
#define NBX 5               /* ceil(512/112) */
#define NBY 11              /* ceil(512/48)  */
#define NTI 32              /* thread-columns (x) == lane id */
#define NTJ 16              /* thread-rows (y)    == warp id */
#define NTHREADS (NTI*NTJ)
#define NCTAS (NBX*NBY*BATCH)   /* 110 <= 148 SMs: co-resident, grid barrier safe */
#define NPH 63                  /* 62*8 + 4 = 500 steps */

typedef unsigned long long ull;

/* scratch state (ping-pong) + premultiplied conductances + barrier flags */
__device__ float g_I0[BATCH*HW];
__device__ float g_I1[BATCH*HW];
__device__ float g_cvL[NCV];
__device__ float g_chL[NCH];
__device__ unsigned g_flags[NCTAS];

/* ---- packed f32x2 helpers (each lane rounds .rn exactly like scalar) ---- */
__device__ __forceinline__ ull pk2(float lo, float hi) {
    ull r; unsigned a = __float_as_uint(lo), b = __float_as_uint(hi);
    asm("mov.b64 %0, {%1, %2};" : "=l"(r) : "r"(a), "r"(b));
    return r;
}
__device__ __forceinline__ void upk2(ull v, float& lo, float& hi) {
    unsigned a, b;
    asm("mov.b64 {%0, %1}, %2;" : "=r"(a), "=r"(b) : "l"(v));
    lo = __uint_as_float(a); hi = __uint_as_float(b);
}
__device__ __forceinline__ ull padd(ull a, ull b) {
    ull d; asm("add.rn.f32x2 %0, %1, %2;" : "=l"(d) : "l"(a), "l"(b)); return d;
}
__device__ __forceinline__ ull pmul(ull a, ull b) {
    ull d; asm("mul.rn.f32x2 %0, %1, %2;" : "=l"(d) : "l"(a), "l"(b)); return d;
}
__device__ __forceinline__ ull pfma(ull a, ull b, ull c) {
    ull d; asm("fma.rn.f32x2 %0, %1, %2, %3;" : "=l"(d) : "l"(a), "l"(b), "l"(c)); return d;
}
#define NEG1 0xBF800000BF800000ULL      /* (-1.0f, -1.0f) */
/* exact packed subtraction a-b: (-1)*b exact, single .rn round == sub */
__device__ __forceinline__ ull psub(ull a, ull b) { return pfma(NEG1, b, a); }

/* ---- conductance kernels: raw g to d_out region, L*g to scratch ---- */
__global__ void k_coeff_v(const float* __restrict__ guide, float* __restrict__ out_cv) {
    int idx = blockIdx.x*blockDim.x + threadIdx.x;
    if (idx >= NCV) return;
    int x = idx % W;
    int y = (idx / W) % (H-1);
    int b = idx / (W*(H-1));
    const float* gb = guide + (size_t)b*3*HW + (size_t)y*W + x;
    float s = 0.f;
    #pragma unroll
    for (int c = 0; c < 3; c++) s += fabsf(gb[(size_t)c*HW + W] - gb[(size_t)c*HW]);
    float m = s * (1.0f/3.0f);
    float g = 1.0f / (1.0f + (m*m)/KK);
    out_cv[idx] = g;
    g_cvL[idx]  = L_STEP * g;
}

__global__ void k_coeff_h(const float* __restrict__ guide, float* __restrict__ out_ch) {
    int idx = blockIdx.x*blockDim.x + threadIdx.x;
    if (idx >= NCH) return;
    int x = idx % (W-1);
    int y = (idx / (W-1)) % H;
    int b = idx / ((W-1)*H);
    const float* gb = guide + (size_t)b*3*HW + (size_t)y*W + x;
    float s = 0.f;
    #pragma unroll
    for (int c = 0; c < 3; c++) s += fabsf(gb[(size_t)c*HW + 1] - gb[(size_t)c*HW]);
    float m = s * (1.0f/3.0f);
    float g = 1.0f / (1.0f + (m*m)/KK);
    out_ch[idx] = g;
    g_chL[idx]  = L_STEP * g;
}

__global__ void k_reset() {
    int idx = threadIdx.x;
    if (idx < NCTAS) g_flags[idx] = 0u;
}

__device__ __forceinline__ void flag_store_release(unsigned* p, unsigned v) {
    asm volatile("st.release.gpu.u32 [%0], %1;" :: "l"(p), "r"(v) : "memory");
}
__device__ __forceinline__ unsigned flag_load_acquire(const unsigned* p) {
    unsigned v;
    asm volatile("ld.acquire.gpu.u32 %0, [%1];" : "=r"(v) : "l"(p) : "memory");
    return v;
}

/* software grid barrier: all NCTAS CTAs co-resident (1 CTA/SM, 110<=148). */
__device__ __forceinline__ void grid_barrier(int cta, unsigned target) {
    __syncthreads();
    if (threadIdx.x == 0) flag_store_release(&g_flags[cta], target);
    if (threadIdx.x < NCTAS) {
        while (flag_load_acquire(&g_flags[threadIdx.x]) < target) { __nanosleep(32); }
    }
    __syncthreads();
}

/* ---- persistent temporal-blocked diffusion, packed f32x2 math ----
 * Thread-private 4x4 block held as 4 rows x 2 packed f32x2 pairs. Coefficients
 * packed likewise and register-resident for all 500 steps. Per step:
 * top/bottom perimeter via double-buffered smem (one __syncthreads),
 * left/right via warp shuffles. Every op order/rounding matches the scalar
 * reference exactly (psub is exact). */
__global__ void __launch_bounds__(NTHREADS, 1)
k_persist(const float* __restrict__ initial, float* __restrict__ out_y) {
    __shared__ float sTop[2][NTJ][TW];
    __shared__ float sBot[2][NTJ][TW];

    const int tid = threadIdx.x;
    const int ti  = tid & 31;
    const int tj  = tid >> 5;
    const int bx = blockIdx.x, by = blockIdx.y, b = blockIdx.z;
    const int cta = bx + NBX*(by + NBY*b);

    const int ox  = bx*TSX - HALO;
    const int oy  = by*TSY - HALO;
    const int lx0 = ti*4, ly0 = tj*4;
    const int gx0 = ox + lx0;
    const int gy0 = oy + ly0;
    const bool xok = (gx0 >= 0) && (gx0 + 4 <= W);

    const float* __restrict__ cvb = g_cvL + (size_t)b*(H-1)*W;
    const float* __restrict__ chb = g_chL + (size_t)b*H*(W-1);

    /* persistent packed coefficients: CVP[r] covers rows gy0-1..gy0+3 */
    ull CVP[5][2];
    #pragma unroll
    for (int jj = 0; jj < 5; jj++) {
        int r = gy0 - 1 + jj;
        if (xok && r >= 0 && r < H-1) {
            ulonglong2 v = *(const ulonglong2*)(cvb + (size_t)r*W + gx0);
            CVP[jj][0] = v.x; CVP[jj][1] = v.y;
        } else { CVP[jj][0] = 0ull; CVP[jj][1] = 0ull; }
    }
    /* CHP[j][0]=(c@gx0-1, c@gx0), CHP[j][1]=(c@gx0+1, c@gx0+2), ch4=c@gx0+3 */
    ull CHP[4][2]; float ch4[4];
    #pragma unroll
    for (int j = 0; j < 4; j++) {
        int gy = gy0 + j;
        float c[5];
        #pragma unroll
        for (int ii = 0; ii < 5; ii++) {
            int cc = gx0 - 1 + ii;
            c[ii] = (gy >= 0 && gy < H && cc >= 0 && cc < W-1)
                  ? chb[(size_t)gy*(W-1) + cc] : 0.f;
        }
        CHP[j][0] = pk2(c[0], c[1]);
        CHP[j][1] = pk2(c[2], c[3]);
        ch4[j] = c[4];
    }

    /* initial state straight from input, as packed pairs */
    ull P[4][2];
    {
        const float* __restrict__ srcb = initial + (size_t)b*HW;
        #pragma unroll
        for (int j = 0; j < 4; j++) {
            int gy = gy0 + j;
            if (xok && gy >= 0 && gy < H) {
                ulonglong2 v = *(const ulonglong2*)(srcb + (size_t)gy*W + gx0);
                P[j][0] = v.x; P[j][1] = v.y;
            } else { P[j][0] = 0ull; P[j][1] = 0ull; }
        }
    }

    for (int p = 0; p < NPH; p++) {
        const int nsteps = (p == NPH-1) ? 4 : HALO;
        for (int s = 0; s < nsteps; s++) {
            const int bs = s & 1;
            /* publish top/bottom perimeter pairs (pre-update) */
            *(ulonglong2*)&sTop[bs][tj][lx0] = make_ulonglong2(P[0][0], P[0][1]);
            *(ulonglong2*)&sBot[bs][tj][lx0] = make_ulonglong2(P[3][0], P[3][1]);

            /* unpack scalars needed for shuffles + shifted pairs (pre-update) */
            float i0[4], i1[4], i2[4], i3[4];
            #pragma unroll
            for (int j = 0; j < 4; j++) {
                upk2(P[j][0], i0[j], i1[j]);
                upk2(P[j][1], i2[j], i3[j]);
            }
            float lf[4], rt[4];
            #pragma unroll
            for (int j = 0; j < 4; j++) {
                lf[j] = __shfl_up_sync  (0xffffffffu, i3[j], 1);  /* lane0 garbage -> zero coeff */
                rt[j] = __shfl_down_sync(0xffffffffu, i0[j], 1);  /* lane31 garbage -> zero coeff */
            }
            __syncthreads();
            ull U[2], D[2];
            {
                ulonglong2 u = (tj > 0)     ? *(ulonglong2*)&sBot[bs][tj-1][lx0]
                                            : make_ulonglong2(0ull, 0ull);
                ulonglong2 d = (tj < NTJ-1) ? *(ulonglong2*)&sTop[bs][tj+1][lx0]
                                            : make_ulonglong2(0ull, 0ull);
                U[0]=u.x; U[1]=u.y; D[0]=d.x; D[1]=d.y;
            }

            /* vertical: N = (I - f_r) + f_{r+1},  f = CV * dv */
            ull N[4][2];
            #pragma unroll
            for (int q = 0; q < 2; q++) {
                ull d0 = psub(P[0][q], U[q]);
                ull d1 = psub(P[1][q], P[0][q]);
                ull d2 = psub(P[2][q], P[1][q]);
                ull d3 = psub(P[3][q], P[2][q]);
                ull d4 = psub(D[q],    P[3][q]);
                ull f0 = pmul(CVP[0][q], d0);
                ull f1 = pmul(CVP[1][q], d1);
                ull f2 = pmul(CVP[2][q], d2);
                ull f3 = pmul(CVP[3][q], d3);
                ull f4 = pmul(CVP[4][q], d4);
                N[0][q] = padd(psub(P[0][q], f0), f1);
                N[1][q] = padd(psub(P[1][q], f1), f2);
                N[2][q] = padd(psub(P[2][q], f2), f3);
                N[3][q] = padd(psub(P[3][q], f3), f4);
            }

            /* horizontal: dh from pre-update I, applied to N */
            #pragma unroll
            for (int j = 0; j < 4; j++) {
                ull Sa  = pk2(lf[j], i0[j]);         /* (lf, I0) */
                ull Sb  = pk2(i1[j], i2[j]);         /* (I1, I2) */
                ull D01 = psub(P[j][0], Sa);          /* (I0-lf, I1-I0) */
                ull D23 = psub(P[j][1], Sb);          /* (I2-I1, I3-I2) */
                float g4 = rt[j] - i3[j];
                ull F01 = pmul(CHP[j][0], D01);       /* (f0, f1) */
                ull F23 = pmul(CHP[j][1], D23);       /* (f2, f3) */
                float f4 = ch4[j] * g4;
                float f0s, f1s, f2s, f3s;
                upk2(F01, f0s, f1s);
                upk2(F23, f2s, f3s);
                ull Fs01 = pk2(f1s, f2s);
                ull Fs23 = pk2(f3s, f4);
                P[j][0] = padd(psub(N[j][0], F01), Fs01);
                P[j][1] = padd(psub(N[j][1], F23), Fs23);
            }
        }

        /* write interior: last phase straight to output, else ping-pong */
        float* __restrict__ wb = (p == NPH-1)
            ? (out_y + (size_t)b*HW)
            : (((p & 1) ? g_I0 : g_I1) + (size_t)b*HW);
        if (xok && lx0 >= HALO && lx0 < TW - HALO) {
            #pragma unroll
            for (int j = 0; j < 4; j++) {
                int ly = ly0 + j;
                int gy = gy0 + j;
                if (ly >= HALO && ly < TH - HALO && gy < H) {
                    *(ulonglong2*)(wb + (size_t)gy*W + gx0) =
                        make_ulonglong2(P[j][0], P[j][1]);
                }
            }
        }

        if (p < NPH-1) {
            grid_barrier(cta, (unsigned)(p + 1));
            const float* __restrict__ rb = ((p & 1) ? g_I0 : g_I1) + (size_t)b*HW;
            #pragma unroll
            for (int j = 0; j < 4; j++) {
                int gy = gy0 + j;
                if (xok && gy >= 0 && gy < H) {
                    ulonglong2 v = *(const ulonglong2*)(rb + (size_t)gy*W + gx0);
                    P[j][0] = v.x; P[j][1] = v.y;
                } else { P[j][0] = 0ull; P[j][1] = 0ull; }
            }
        }
    }
}

extern "C" void kernel_launch(void* const* d_in, const int* in_sizes, int n_in,
                              void* d_out, int out_size) {
    const float* a0 = (const float*)d_in[0];
    const float* a1 = (const float*)d_in[1];
    const float* guide = a0;
    const float* initial = a1;
    if (n_in >= 2 && in_sizes[0] < in_sizes[1]) { guide = a1; initial = a0; }

    float* out    = (float*)d_out;
    float* out_y  = out;                       /* [BATCH*HW]   */
    float* out_cv = out + BATCH*HW;            /* [NCV]        */
    float* out_ch = out_cv + NCV;              /* [NCH]        */

    k_reset<<<1, 128>>>();
    k_coeff_v<<<(NCV + 255)/256, 256>>>(guide, out_cv);
    k_coeff_h<<<(NCH + 255)/256, 256>>>(guide, out_ch);

    dim3 grid(NBX, NBY, BATCH);
    k_persist<<<grid, NTHREADS>>>(initial, out_y);
}